// round 17
// baseline (speedup 1.0000x reference)
#include <cuda_runtime.h>

// HoG layer, fused. Rectangular 32x16-cell tiles -> 512 CTAs, fully resident
// in ONE wave at 4 CTAs/SM (no tail). 3 cells/thread (36 LDGs in flight).
// Phase 1:   scattered gather, all-9-bin hist writes + per-cell ssq.
// Phase 1.5: one inv = 1/(sqrt(ssq)+eps) per block (2/thread).
// Phase 2:   warp-per-block contiguous 144B stores (proven R14/R16).
//   input  x: (1, 3, 4096, 4096) f32 ; output feat: (511, 511, 36) f32

#define IMG   4096
#define CELLS 512
#define OUTD  511
#define TCX   32
#define TCY   16
#define HWX   (TCX + 1)     // 33
#define HWY   (TCY + 1)     // 17
#define NCELL (HWX * HWY)   // 561
#define NT    256
#define PC    3             // cells per thread (3*256 = 768 >= 561)

__global__ __launch_bounds__(NT, 4)
void hog_fused_kernel(const float* __restrict__ x, float* __restrict__ out)
{
    __shared__ __align__(16) float hist[NCELL * 9];   // 20196 B
    __shared__ float cssq[NCELL];                     // 2244 B
    __shared__ float binv[TCY * TCX];                 // 2048 B

    const int cx0 = blockIdx.x * TCX;
    const int cy0 = blockIdx.y * TCY;
    const int tid = threadIdx.x;
    const long chs = (long)IMG * IMG;

    // ---- Phase 1: PC cells per thread, all 36 loads issued up front ----
    float v[PC][12];
    bool  valid[PC];
    const float* base[PC];
    bool  hd[PC], hr[PC];

    #pragma unroll
    for (int it = 0; it < PC; it++) {
        const int c = tid + it * NT;
        const int lcy = c / HWX;
        const int lcx = c - lcy * HWX;
        const int cy = cy0 + lcy;
        const int cx = cx0 + lcx;
        valid[it] = (c < NCELL) && (cy < CELLS) && (cx < CELLS);
        const int py = cy * 8 + 7;
        const int px = cx * 8 + 7;
        base[it] = x + (long)py * IMG + px;
        hd[it] = (py + 1 < IMG);
        hr[it] = (px + 1 < IMG);
    }

    #pragma unroll
    for (int it = 0; it < PC; it++) {
        const float* p = base[it];
        const bool va = valid[it];
        const bool vd = va && hd[it];
        const bool vr = va && hr[it];
        #pragma unroll
        for (int ch = 0; ch < 3; ch++) {
            const float* pc = p + ch * chs;
            v[it][ch * 4 + 0] = va ? pc[-IMG] : 0.0f;
            v[it][ch * 4 + 1] = va ? pc[-1]   : 0.0f;
            v[it][ch * 4 + 2] = vd ? pc[IMG]  : 0.0f;
            v[it][ch * 4 + 3] = vr ? pc[1]    : 0.0f;
        }
    }

    #pragma unroll
    for (int it = 0; it < PC; it++) {
        if (!valid[it]) continue;
        const float su = v[it][0] + v[it][4] + v[it][8];
        const float sl = v[it][1] + v[it][5] + v[it][9];
        const float sd = v[it][2] + v[it][6] + v[it][10];
        const float sr = v[it][3] + v[it][7] + v[it][11];

        const float gv = sd - su;
        const float gh = sr - sl;
        const float mag = sqrtf(gv * gv + gh * gh + 1e-6f);
        const float ang = fabsf(atanf(gh / (gv + 1e-9f)))
                          * (180.0f / 3.14159265358979323846f);

        const float t  = ang * 0.05f;                 // ang / 20
        const int   ji = (int)floorf(t - 0.5f);       // in [-1, 4]
        const float vj  = mag * ((float)ji + 1.5f - t);
        const float vj1 = mag - vj;

        const int i0 = (ji < 0) ? 8 : ji;   // mod(ji, 9)
        const int i1 = ji + 1;              // never == i0
        const int c  = tid + it * NT;
        float* hrow = &hist[c * 9];
        #pragma unroll
        for (int b = 0; b < 9; b++)
            hrow[b] = (b == i0) ? vj : ((b == i1) ? vj1 : 0.0f);
        cssq[c] = vj * vj + vj1 * vj1;
    }
    __syncthreads();

    // ---- Phase 1.5: block inverses (512 blocks, 2 per thread) ----
    #pragma unroll
    for (int k = 0; k < 2; k++) {
        const int o  = tid + k * NT;        // 0..511
        const int ly = o >> 5;              // /32
        const int lx = o & 31;
        const int cbase = ly * HWX + lx;
        const float ss = cssq[cbase] + cssq[cbase + 1]
                       + cssq[cbase + HWX] + cssq[cbase + HWX + 1];
        binv[o] = 1.0f / (sqrtf(ss) + 1e-9f);
    }
    __syncthreads();

    // ---- Phase 2: warp per 2 output rows (32 blocks each), contiguous ----
    const int warp = tid >> 5;
    const int lane = tid & 31;

    // lane -> hist offsets: comp `lane` (0..31) and comp `32+lane` (lanes 0..3)
    const int s1 = lane / 9;
    const int b1 = lane - s1 * 9;
    const int off1 = ((s1 & 1) ? 9 : 0) + ((s1 & 2) ? HWX * 9 : 0) + b1;
    const int off2 = HWX * 9 + 9 + 5 + lane;  // comps 32..35: seg h11, bins 5..8

    const int nlx = (cx0 + TCX <= OUTD) ? TCX : (OUTD - cx0);   // 32 or 31

    #pragma unroll
    for (int ry = 0; ry < 2; ry++) {
        const int ly = 2 * warp + ry;
        const int oy = cy0 + ly;
        if (oy >= OUTD) continue;
        float* orow = out + ((size_t)oy * OUTD + cx0) * 36;
        const int hbase = ly * HWX;
        const int bbase = ly * TCX;

        #pragma unroll 2
        for (int lx = 0; lx < nlx; lx++) {
            const float inv = binv[bbase + lx];            // broadcast LDS
            const float* hb = &hist[(hbase + lx) * 9];
            const float w1 = hb[off1] * inv;
            float* ob = orow + lx * 36;
            ob[lane] = w1;
            if (lane < 4)
                ob[32 + lane] = hb[off2] * inv;
        }
    }
}

extern "C" void kernel_launch(void* const* d_in, const int* in_sizes, int n_in,
                              void* d_out, int out_size)
{
    const float* x = (const float*)d_in[0];
    float* out = (float*)d_out;
    dim3 grid(CELLS / TCX, CELLS / TCY);   // 16 x 32 = 512 CTAs
    hog_fused_kernel<<<grid, NT>>>(x, out);
}